// round 1
// baseline (speedup 1.0000x reference)
#include <cuda_runtime.h>
#include <math.h>

#define NPTS      524288
#define GRIDSZ    512
#define NC        36
#define KIN       129
#define NK1       17          // ceil(136/8)
#define HID       256
#define NOUT      129
#define NOUT_PAD  144
#define NK2       32          // 256/8
#define TB        128
#define NTHREADS  512

#define HS_STRIDE 140         // 140 % 32 = 12 -> conflict-free A frags
#define H1_STRIDE 260         // 260 % 32 = 4  -> conflict-free A frags
#define WS_STRIDE 264         // 264 % 32 = 8  -> conflict-free B frags
#define WS_BUF    (8*WS_STRIDE)              // 2112 floats per slab
#define SM_A_FLOATS (TB*H1_STRIDE)           // 33280 (union: hs then h1s)
#define SM_WS_OFF   SM_A_FLOATS
#define SM_B1_OFF   (SM_WS_OFF + 2*WS_BUF)   // 37504
#define SM_B2_OFF   (SM_B1_OFF + HID)        // 37760
#define SM_FLOATS   (SM_B2_OFF + NOUT_PAD)   // 37904
#define SMEM_BYTES  (SM_FLOATS*4)            // 151616 B

// channel-last scratch (device globals are the sanctioned scratch mechanism)
__device__ float g_planesT[3*GRIDSZ*GRIDSZ*NC];   // [i][y][x][c]
__device__ float g_linesT[3*GRIDSZ*NC];           // [i][l][c]

__global__ void transpose_kernel(const float* __restrict__ planes,
                                 const float* __restrict__ lines) {
    int tid = blockIdx.x * blockDim.x + threadIdx.x;
    const int NPLANE = 3*GRIDSZ*GRIDSZ;
    if (tid < NPLANE) {
        int x = tid & (GRIDSZ-1);
        int y = (tid >> 9) & (GRIDSZ-1);
        int i = tid / (GRIDSZ*GRIDSZ);
        float* dst = g_planesT + tid*NC;
        const float* src = planes + ((long)i*NC*GRIDSZ*GRIDSZ) + (long)y*GRIDSZ + x;
        #pragma unroll
        for (int c = 0; c < NC; c++)
            dst[c] = src[(long)c*GRIDSZ*GRIDSZ];
    } else {
        int t2 = tid - NPLANE;
        if (t2 < 3*GRIDSZ) {
            int j = t2 & (GRIDSZ-1);
            int i = t2 >> 9;
            float* dst = g_linesT + t2*NC;
            const float* src = lines + (long)i*NC*GRIDSZ + j;
            #pragma unroll
            for (int c = 0; c < NC; c++)
                dst[c] = src[(long)c*GRIDSZ];
        }
    }
}

__device__ __forceinline__ unsigned f2tf(float x) {
    unsigned r; asm("cvt.rna.tf32.f32 %0, %1;" : "=r"(r) : "f"(x)); return r;
}
__device__ __forceinline__ float f2tff(float x) { return __uint_as_float(f2tf(x)); }

__device__ __forceinline__ void mma_tf32(float c[4], unsigned a0, unsigned a1,
                                         unsigned a2, unsigned a3,
                                         unsigned b0, unsigned b1) {
    asm volatile(
        "mma.sync.aligned.m16n8k8.row.col.f32.tf32.tf32.f32 "
        "{%0,%1,%2,%3},{%4,%5,%6,%7},{%8,%9},{%0,%1,%2,%3};"
        : "+f"(c[0]), "+f"(c[1]), "+f"(c[2]), "+f"(c[3])
        : "r"(a0), "r"(a1), "r"(a2), "r"(a3), "r"(b0), "r"(b1));
}

__device__ __forceinline__ float softplus100(float z) {
    float y = 100.f * z;
    return 0.01f * (fmaxf(y, 0.f) + log1pf(__expf(-fabsf(y))));
}

__global__ void __launch_bounds__(NTHREADS, 1)
tensosdf_main(const float* __restrict__ xyz,
              const float* __restrict__ W1, const float* __restrict__ b1,
              const float* __restrict__ W2, const float* __restrict__ b2,
              float* __restrict__ out) {
    extern __shared__ float smem[];
    float* sA  = smem;                 // hs[128][140] then h1s[128][260] (temporally disjoint)
    float* ws  = smem + SM_WS_OFF;     // weight slab double buffer
    float* b1s = smem + SM_B1_OFF;
    float* b2s = smem + SM_B2_OFF;

    const int tid  = threadIdx.x;
    const int lane = tid & 31;
    const int warp = tid >> 5;
    const int pbase = blockIdx.x * TB;

    // ---- stage biases ----
    if (tid < HID) b1s[tid] = b1[tid];
    else if (tid < HID + NOUT_PAD) {
        int c = tid - HID;
        b2s[c] = (c < NOUT) ? b2[c] : 0.f;
    }

    // ---- gather phase: 4 threads per point ----
    {
        const int p   = tid >> 2;
        const int sub = tid & 3;
        const int gp  = pbase + p;
        float xn[3];
        xn[0] = 2.f * xyz[gp*3+0] - 1.f;
        xn[1] = 2.f * xyz[gp*3+1] - 1.f;
        xn[2] = 2.f * xyz[gp*3+2] - 1.f;
        float* hrow = sA + p * HS_STRIDE;

        const int m0s[3] = {0, 0, 1};
        const int m1s[3] = {1, 2, 2};
        const int vms[3] = {2, 1, 0};
        #pragma unroll
        for (int i = 0; i < 3; i++) {
            float gx = xn[m0s[i]], gy = xn[m1s[i]], gl = xn[vms[i]];
            float px = (gx + 1.f) * 0.5f * 511.f;
            float py = (gy + 1.f) * 0.5f * 511.f;
            float pl = (gl + 1.f) * 0.5f * 511.f;
            int ix = min(max((int)floorf(px), 0), 510);
            int iy = min(max((int)floorf(py), 0), 510);
            int il = min(max((int)floorf(pl), 0), 510);
            float wx = px - (float)ix, wy = py - (float)iy, wl = pl - (float)il;
            const float* pb = g_planesT + (((i*GRIDSZ + iy)*GRIDSZ) + ix) * NC;
            const float* lb = g_linesT + (i*GRIDSZ + il) * NC;
            #pragma unroll
            for (int j = 0; j < 9; j++) {
                int c = sub * 9 + j;
                float f00 = pb[c];
                float f01 = pb[NC + c];
                float f10 = pb[GRIDSZ*NC + c];
                float f11 = pb[GRIDSZ*NC + NC + c];
                float fx0 = f00 + wx * (f01 - f00);
                float fx1 = f10 + wx * (f11 - f10);
                float pf  = fx0 + wy * (fx1 - fx0);
                float l0  = lb[c];
                float lf  = l0 + wl * (lb[NC + c] - l0);
                hrow[i*NC + c] = f2tff(pf * lf);
            }
        }
        if (sub < 3) {   // positional encoding, dim d = sub
            float v = xn[sub];
            hrow[108 + sub] = f2tff(v);
            float fr = 1.f;
            #pragma unroll
            for (int fi = 0; fi < 3; fi++) {
                float s, c;
                sincosf(v * fr, &s, &c);
                hrow[111 + 6*fi + sub] = f2tff(s);
                hrow[114 + 6*fi + sub] = f2tff(c);
                fr *= 2.f;
            }
        } else {         // zero-pad K 129..139
            #pragma unroll
            for (int c = KIN; c < HS_STRIDE; c++) hrow[c] = 0.f;
        }
    }

    // warp tiling: 8 m-tiles x 2 n-halves
    const int mt = warp & 7;
    const int nh = warp >> 3;
    const int arow = mt * 16;
    const int g = lane >> 2;
    const int t = lane & 3;

    auto stage1 = [&](int ks, int buf) {
        int k0 = ks * 8;
        #pragma unroll
        for (int e = 0; e < 4; e++) {
            int idx = tid + e * NTHREADS;      // 0..2047
            int kk = idx >> 8, n = idx & 255;
            int k = k0 + kk;
            float v = (k < KIN) ? W1[k*HID + n] : 0.f;
            ws[buf*WS_BUF + kk*WS_STRIDE + n] = f2tff(v);
        }
    };

    stage1(0, 0);
    __syncthreads();

    // ================= GEMM1: h1 = softplus(hs @ W1 + b1) =================
    float acc[16][4];
    #pragma unroll
    for (int i = 0; i < 16; i++)
        #pragma unroll
        for (int j = 0; j < 4; j++) acc[i][j] = 0.f;

    for (int ks = 0; ks < NK1; ks++) {
        int buf = ks & 1;
        if (ks + 1 < NK1) stage1(ks + 1, buf ^ 1);
        const float* Ab = sA + (arow + g) * HS_STRIDE + ks*8 + t;
        unsigned a0 = __float_as_uint(Ab[0]);
        unsigned a2 = __float_as_uint(Ab[4]);
        unsigned a1 = __float_as_uint(Ab[8*HS_STRIDE]);
        unsigned a3 = __float_as_uint(Ab[8*HS_STRIDE + 4]);
        const float* Bb = ws + buf*WS_BUF + t*WS_STRIDE + nh*128 + g;
        #pragma unroll
        for (int nt = 0; nt < 16; nt++) {
            unsigned bb0 = __float_as_uint(Bb[nt*8]);
            unsigned bb1 = __float_as_uint(Bb[4*WS_STRIDE + nt*8]);
            mma_tf32(acc[nt], a0, a1, a2, a3, bb0, bb1);
        }
        __syncthreads();
    }

    // epilogue: bias + softplus -> h1s (tf32-rounded)
    #pragma unroll
    for (int nt = 0; nt < 16; nt++) {
        int col = nh*128 + nt*8 + 2*t;
        float bb0 = b1s[col], bb1 = b1s[col + 1];
        float r0 = softplus100(acc[nt][0] + bb0);
        float r1 = softplus100(acc[nt][1] + bb1);
        float r2 = softplus100(acc[nt][2] + bb0);
        float r3 = softplus100(acc[nt][3] + bb1);
        float2* d0 = (float2*)(sA + (arow + g) * H1_STRIDE + col);
        *d0 = make_float2(f2tff(r0), f2tff(r1));
        float2* d1 = (float2*)(sA + (arow + g + 8) * H1_STRIDE + col);
        *d1 = make_float2(f2tff(r2), f2tff(r3));
    }

    auto stage2 = [&](int ks, int buf) {
        int k0 = ks * 8;
        for (int idx = tid; idx < 8*NOUT_PAD; idx += NTHREADS) {
            int kk = idx / NOUT_PAD, n = idx - kk*NOUT_PAD;
            float v = (n < NOUT) ? W2[(k0 + kk)*NOUT + n] : 0.f;
            ws[buf*WS_BUF + kk*WS_STRIDE + n] = f2tff(v);
        }
    };

    stage2(0, 0);
    __syncthreads();

    // ================= GEMM2: out = h1 @ W2 + b2 =================
    float acc2[9][4];
    #pragma unroll
    for (int i = 0; i < 9; i++)
        #pragma unroll
        for (int j = 0; j < 4; j++) acc2[i][j] = 0.f;

    for (int ks = 0; ks < NK2; ks++) {
        int buf = ks & 1;
        if (ks + 1 < NK2) stage2(ks + 1, buf ^ 1);
        const float* Ab = sA + (arow + g) * H1_STRIDE + ks*8 + t;
        unsigned a0 = __float_as_uint(Ab[0]);
        unsigned a2 = __float_as_uint(Ab[4]);
        unsigned a1 = __float_as_uint(Ab[8*H1_STRIDE]);
        unsigned a3 = __float_as_uint(Ab[8*H1_STRIDE + 4]);
        const float* Bb = ws + buf*WS_BUF + t*WS_STRIDE + nh*72 + g;
        #pragma unroll
        for (int nt = 0; nt < 9; nt++) {
            unsigned bb0 = __float_as_uint(Bb[nt*8]);
            unsigned bb1 = __float_as_uint(Bb[4*WS_STRIDE + nt*8]);
            mma_tf32(acc2[nt], a0, a1, a2, a3, bb0, bb1);
        }
        __syncthreads();
    }

    // epilogue: bias + global store (scalar stores: point stride 129 floats breaks v2 alignment)
    #pragma unroll
    for (int nt = 0; nt < 9; nt++) {
        int col = nh*72 + nt*8 + 2*t;
        float o0 = acc2[nt][0] + b2s[col];
        float o1 = acc2[nt][1] + b2s[col + 1];
        float o2 = acc2[nt][2] + b2s[col];
        float o3 = acc2[nt][3] + b2s[col + 1];
        int r0 = (pbase + arow + g) * NOUT;
        int r1 = (pbase + arow + g + 8) * NOUT;
        if (col < NOUT)     { out[r0 + col]     = o0; out[r1 + col]     = o2; }
        if (col + 1 < NOUT) { out[r0 + col + 1] = o1; out[r1 + col + 1] = o3; }
    }
}

extern "C" void kernel_launch(void* const* d_in, const int* in_sizes, int n_in,
                              void* d_out, int out_size) {
    const float* xyz    = (const float*)d_in[0];
    const float* planes = (const float*)d_in[1];
    const float* lines  = (const float*)d_in[2];
    const float* W1     = (const float*)d_in[3];
    const float* b1     = (const float*)d_in[4];
    const float* W2     = (const float*)d_in[5];
    const float* b2     = (const float*)d_in[6];
    float* out = (float*)d_out;

    static bool attr_set = false;
    if (!attr_set) {
        cudaFuncSetAttribute(tensosdf_main,
                             cudaFuncAttributeMaxDynamicSharedMemorySize, SMEM_BYTES);
        attr_set = true;
    }

    const int ntrans = 3*GRIDSZ*GRIDSZ + 3*GRIDSZ;
    transpose_kernel<<<(ntrans + 255) / 256, 256>>>(planes, lines);
    tensosdf_main<<<NPTS / TB, NTHREADS, SMEM_BYTES>>>(xyz, W1, b1, W2, b2, out);
}